// round 16
// baseline (speedup 1.0000x reference)
#include <cuda_runtime.h>
#include <cuda_bf16.h>
#include <cstdint>

#define Bsz 64
#define Ssz 2048
#define Isz 512
#define Hsz 512

// ============================================================
// Scratch: bf16 hi/lo decompositions (device globals — allowed).
// ============================================================
__device__ __nv_bfloat16 g_xhi[(size_t)Bsz * Ssz * Isz];   // 128 MB
__device__ __nv_bfloat16 g_xlo[(size_t)Bsz * Ssz * Isz];   // 128 MB
__device__ __nv_bfloat16 g_wthi[Isz * Hsz];                // W^T [n][k]
__device__ __nv_bfloat16 g_wtlo[Isz * Hsz];

// ============================================================
// Conversion kernels: fp32 -> (hi, lo) bf16.
// ============================================================
__global__ __launch_bounds__(256) void conv_x(const float* __restrict__ x) {
    const size_t i = ((size_t)blockIdx.x * 256 + threadIdx.x) * 4;
    float4 v = *(const float4*)(x + i);
    float vv[4] = {v.x, v.y, v.z, v.w};
    unsigned short hh[4], ll[4];
#pragma unroll
    for (int j = 0; j < 4; j++) {
        __nv_bfloat16 h = __float2bfloat16_rn(vv[j]);
        float lo = vv[j] - __bfloat162float(h);
        __nv_bfloat16 l = __float2bfloat16_rn(lo);
        hh[j] = *(unsigned short*)&h;
        ll[j] = *(unsigned short*)&l;
    }
    uint2 ph, pl;
    ph.x = (uint32_t)hh[0] | ((uint32_t)hh[1] << 16);
    ph.y = (uint32_t)hh[2] | ((uint32_t)hh[3] << 16);
    pl.x = (uint32_t)ll[0] | ((uint32_t)ll[1] << 16);
    pl.y = (uint32_t)ll[2] | ((uint32_t)ll[3] << 16);
    *(uint2*)(g_xhi + i) = ph;
    *(uint2*)(g_xlo + i) = pl;
}

__global__ __launch_bounds__(256) void conv_w(const float* __restrict__ W) {
    const int idx = blockIdx.x * 256 + threadIdx.x;   // 262144 total
    const int k = idx >> 9, n = idx & 511;
    float v = W[idx];                                  // W[k][n]
    __nv_bfloat16 h = __float2bfloat16_rn(v);
    float lo = v - __bfloat162float(h);
    __nv_bfloat16 l = __float2bfloat16_rn(lo);
    g_wthi[n * 512 + k] = h;                           // W^T [n][k]
    g_wtlo[n * 512 + k] = l;
}

// ============================================================
// Phase 1 GEMM: xW + b via mma.sync.m16n8k16 (bf16x3 compensated).
// CTA 128M x 64N, 8 warps (4m x 2n), warp tile 32x32.
// Fragments loaded directly from global bf16 scratch.
// ============================================================
#define MMA_BF16(c, a, b)                                              \
    asm volatile(                                                      \
        "mma.sync.aligned.m16n8k16.row.col.f32.bf16.bf16.f32 "         \
        "{%0,%1,%2,%3}, {%4,%5,%6,%7}, {%8,%9}, {%0,%1,%2,%3};"        \
        : "+f"((c)[0]), "+f"((c)[1]), "+f"((c)[2]), "+f"((c)[3])       \
        : "r"((a)[0]), "r"((a)[1]), "r"((a)[2]), "r"((a)[3]),          \
          "r"((b)[0]), "r"((b)[1]))

__global__ __launch_bounds__(256, 2) void gemm_mma(
    const float* __restrict__ bias,
    float* __restrict__ C)          // [M,512] = xW+b
{
    const int tid  = threadIdx.x;
    const int wid  = tid >> 5;
    const int lane = tid & 31;
    const int gr   = lane >> 2;     // group row (0..7)
    const int tg   = lane & 3;      // thread in group

    const int m0 = blockIdx.y * 128 + (wid >> 1) * 32;
    const int n0 = blockIdx.x * 64 + (wid & 1) * 32;

    float acc[2][4][4];
#pragma unroll
    for (int mf = 0; mf < 2; mf++)
#pragma unroll
        for (int nf = 0; nf < 4; nf++)
#pragma unroll
            for (int j = 0; j < 4; j++) acc[mf][nf][j] = 0.0f;

    const __nv_bfloat16* __restrict__ xh = g_xhi;
    const __nv_bfloat16* __restrict__ xl = g_xlo;
    const __nv_bfloat16* __restrict__ wh = g_wthi;
    const __nv_bfloat16* __restrict__ wl = g_wtlo;

#pragma unroll 2
    for (int k = 0; k < 512; k += 16) {
        // ---- A fragments (m16n8k16 row-major layout) ----
        uint32_t ah[2][4], al[2][4];
#pragma unroll
        for (int mf = 0; mf < 2; mf++) {
            const size_t base =
                (size_t)(m0 + mf * 16 + gr) * 512 + k + tg * 2;
            ah[mf][0] = *(const uint32_t*)(xh + base);
            ah[mf][1] = *(const uint32_t*)(xh + base + 8 * 512);
            ah[mf][2] = *(const uint32_t*)(xh + base + 8);
            ah[mf][3] = *(const uint32_t*)(xh + base + 8 * 512 + 8);
            al[mf][0] = *(const uint32_t*)(xl + base);
            al[mf][1] = *(const uint32_t*)(xl + base + 8 * 512);
            al[mf][2] = *(const uint32_t*)(xl + base + 8);
            al[mf][3] = *(const uint32_t*)(xl + base + 8 * 512 + 8);
        }
        // ---- B fragments (col-major k16xn8; W^T stored [n][k]) ----
        uint32_t bh[4][2], bl[4][2];
#pragma unroll
        for (int nf = 0; nf < 4; nf++) {
            const size_t base =
                (size_t)(n0 + nf * 8 + gr) * 512 + k + tg * 2;
            bh[nf][0] = *(const uint32_t*)(wh + base);
            bh[nf][1] = *(const uint32_t*)(wh + base + 8);
            bl[nf][0] = *(const uint32_t*)(wl + base);
            bl[nf][1] = *(const uint32_t*)(wl + base + 8);
        }
        // ---- 3-term compensated MMA ----
#pragma unroll
        for (int mf = 0; mf < 2; mf++)
#pragma unroll
            for (int nf = 0; nf < 4; nf++) {
                MMA_BF16(acc[mf][nf], ah[mf], bh[nf]);
                MMA_BF16(acc[mf][nf], ah[mf], bl[nf]);
                MMA_BF16(acc[mf][nf], al[mf], bh[nf]);
            }
    }

    // ---- epilogue: add bias, store fp32 ----
#pragma unroll
    for (int mf = 0; mf < 2; mf++) {
        const int row = m0 + mf * 16 + gr;
#pragma unroll
        for (int nf = 0; nf < 4; nf++) {
            const int col = n0 + nf * 8 + tg * 2;
            const float b0 = __ldg(bias + col);
            const float b1 = __ldg(bias + col + 1);
            float2 r0 = make_float2(acc[mf][nf][0] + b0, acc[mf][nf][1] + b1);
            float2 r1 = make_float2(acc[mf][nf][2] + b0, acc[mf][nf][3] + b1);
            *(float2*)(C + (size_t)row * 512 + col)       = r0;
            *(float2*)(C + (size_t)(row + 8) * 512 + col) = r1;
        }
    }
}

// ============================================================
// fast tanh + mbar_wait (unchanged)
// ============================================================
__device__ __forceinline__ float fast_tanh(float x) {
    float e;
    asm("ex2.approx.f32 %0, %1;" : "=f"(e) : "f"(x * 2.8853900817779268f));
    float r;
    asm("rcp.approx.f32 %0, %1;" : "=f"(r) : "f"(e + 1.0f));
    return fmaf(-2.0f, r, 1.0f);
}

__device__ __forceinline__ void mbar_wait(unsigned int addr, unsigned int parity) {
    unsigned int done;
    do {
        asm volatile(
            "{\n\t.reg .pred p;\n\t"
            "mbarrier.try_wait.parity.acquire.cta.shared::cta.b64 p, [%1], %2, 0x989680;\n\t"
            "selp.b32 %0, 1, 0, p;\n\t}"
            : "=r"(done) : "r"(addr), "r"(parity) : "memory");
    } while (!done);
}

// Dynamic smem layout (bytes) — scan (unchanged R14):
#define HB_OFF   0u
#define STG_OFF  8192u
#define RED_OFF  9216u
#define MB_OFF   17408u
#define USM_OFF  17536u
#define SMEM_TOTAL 83072

// ============================================================
// Phase 2: persistent cluster RNN scan — R14 winner, verbatim.
// ============================================================
__global__ void __launch_bounds__(256, 2) __cluster_dims__(8, 1, 1)
rnn_scan(const float* __restrict__ U,
         float* __restrict__ hidden,
         float* __restrict__ hlast)
{
    extern __shared__ __align__(128) char dsm[];

    const int tid  = threadIdx.x;
    unsigned int rank;
    asm("mov.u32 %0, %%cluster_ctarank;" : "=r"(rank));
    const int cid  = blockIdx.x >> 3;
    const int b0   = cid * 2;
    const int w    = tid >> 5;
    const int lane = tid & 31;
    const int gc0  = (int)rank * 64 + lane;
    const int gc1  = gc0 + 32;

    unsigned long long* Usm = (unsigned long long*)(dsm + USM_OFF);

    unsigned long long UA[32];
#pragma unroll
    for (int j = 0; j < 32; j++) {
        int k0 = w * 64 + 2 * j;
        unsigned int lo = __float_as_uint(U[(size_t)k0 * Hsz + gc0]);
        unsigned int hi = __float_as_uint(U[(size_t)(k0 + 1) * Hsz + gc0]);
        asm("mov.b64 %0, {%1, %2};" : "=l"(UA[j]) : "r"(lo), "r"(hi));
    }
    for (int j = 0; j < 32; j++) {
        int k0 = w * 64 + 2 * j;
        unsigned int lo = __float_as_uint(U[(size_t)k0 * Hsz + gc1]);
        unsigned int hi = __float_as_uint(U[(size_t)(k0 + 1) * Hsz + gc1]);
        unsigned long long u;
        asm("mov.b64 %0, {%1, %2};" : "=l"(u) : "r"(lo), "r"(hi));
        Usm[j * 256 + tid] = u;
    }

    const unsigned int hb_base =
        (unsigned int)__cvta_generic_to_shared(dsm + HB_OFF);
    const unsigned int stg_base =
        (unsigned int)__cvta_generic_to_shared(dsm + STG_OFF);
    const unsigned int mb_base =
        (unsigned int)__cvta_generic_to_shared(dsm + MB_OFF);
    float* redp = (float*)(dsm + RED_OFF);

    const unsigned int my_mb = mb_base + (unsigned int)w * 16u;

    {
        float* hz = (float*)(dsm + HB_OFF);
        for (int i = tid; i < 2048; i += 256) hz[i] = 0.0f;
    }
    if (tid == 0) {
#pragma unroll
        for (int qq = 0; qq < 8; qq++) {
#pragma unroll
            for (int b = 0; b < 2; b++)
                asm volatile("mbarrier.init.shared.b64 [%0], %1;"
                             :: "r"(mb_base + qq * 16u + b * 8u), "r"(1u)
                             : "memory");
            asm volatile("mbarrier.arrive.expect_tx.shared.b64 _, [%0], %1;"
                         :: "r"(mb_base + qq * 16u + 8u), "r"(512u) : "memory");
        }
    }
    __syncthreads();
    asm volatile("barrier.cluster.arrive.aligned;" ::: "memory");
    asm volatile("barrier.cluster.wait.aligned;" ::: "memory");

    const int ec  = tid & 63;
    const int eb  = (tid >> 6) & 1;
    const int egc = (int)rank * 64 + ec;
    const int ecomp = (ec >> 5) * 2 + eb;
    const int elane = ec & 31;
    size_t gaddr = 0;
    if (tid < 128)
        gaddr = ((size_t)(b0 + eb) * Ssz) * Hsz + egc;

    unsigned int ph0 = 0, ph1 = 0;

    for (int t = 0; t < Ssz; t++) {
        const int q = t & 1;
        const unsigned int mbq = my_mb + (unsigned int)q * 8u;

        float xw = 0.0f;
        if (tid < 128)
            xw = __ldg(hidden + gaddr);

        if (t > 0) {
            if (q == 0) { mbar_wait(mbq, ph0); ph0 ^= 1; }
            else        { mbar_wait(mbq, ph1); ph1 ^= 1; }
        }
        if (lane == 0)
            asm volatile("mbarrier.arrive.expect_tx.shared.b64 _, [%0], %1;"
                         :: "r"(mbq), "r"(512u) : "memory");

        const ulonglong2* hk =
            (const ulonglong2*)(dsm + HB_OFF + q * 4096 + w * 512);
        unsigned long long a0 = 0ull, a1 = 0ull, a2 = 0ull, a3 = 0ull;
#pragma unroll
        for (int j = 0; j < 32; j++) {
            ulonglong2 p = hk[j];
            unsigned long long ub = Usm[j * 256 + tid];
            asm("fma.rn.f32x2 %0, %1, %2, %0;" : "+l"(a0) : "l"(UA[j]), "l"(p.x));
            asm("fma.rn.f32x2 %0, %1, %2, %0;" : "+l"(a1) : "l"(UA[j]), "l"(p.y));
            asm("fma.rn.f32x2 %0, %1, %2, %0;" : "+l"(a2) : "l"(ub), "l"(p.x));
            asm("fma.rn.f32x2 %0, %1, %2, %0;" : "+l"(a3) : "l"(ub), "l"(p.y));
        }
        float s0, s1, s2, s3;
        {
            unsigned int l, h;
            asm("mov.b64 {%0, %1}, %2;" : "=r"(l), "=r"(h) : "l"(a0));
            s0 = __uint_as_float(l) + __uint_as_float(h);
            asm("mov.b64 {%0, %1}, %2;" : "=r"(l), "=r"(h) : "l"(a1));
            s1 = __uint_as_float(l) + __uint_as_float(h);
            asm("mov.b64 {%0, %1}, %2;" : "=r"(l), "=r"(h) : "l"(a2));
            s2 = __uint_as_float(l) + __uint_as_float(h);
            asm("mov.b64 {%0, %1}, %2;" : "=r"(l), "=r"(h) : "l"(a3));
            s3 = __uint_as_float(l) + __uint_as_float(h);
        }

        float* rq = redp + q * 1024;
        if (tid >= 128) {
            if (t > 0)
                asm volatile("bar.sync 3, 256;" ::: "memory");
            rq[(0 * 8 + w) * 32 + lane] = s0;
            rq[(1 * 8 + w) * 32 + lane] = s1;
            rq[(2 * 8 + w) * 32 + lane] = s2;
            rq[(3 * 8 + w) * 32 + lane] = s3;
            asm volatile("bar.arrive 2, 256;" ::: "memory");
        } else {
            rq[(0 * 8 + w) * 32 + lane] = s0;
            rq[(1 * 8 + w) * 32 + lane] = s1;
            rq[(2 * 8 + w) * 32 + lane] = s2;
            rq[(3 * 8 + w) * 32 + lane] = s3;
            asm volatile("bar.sync 2, 256;" ::: "memory");

            const float* rr = rq + ecomp * 256 + elane;
            float v = xw + (((rr[0 * 32] + rr[1 * 32]) +
                             (rr[2 * 32] + rr[3 * 32])) +
                            ((rr[4 * 32] + rr[5 * 32]) +
                             (rr[6 * 32] + rr[7 * 32])));
            v = fast_tanh(v);
            asm volatile("bar.arrive 3, 256;" ::: "memory");

            *(float*)(dsm + STG_OFF + (q ^ 1) * 512 +
                      (ec >> 1) * 16 + eb * 8 + (ec & 1) * 4) = v;

            hidden[gaddr] = v;
            if (t == Ssz - 1)
                hlast[(size_t)(b0 + eb) * Hsz + egc] = v;
            else
                gaddr += Hsz;

            asm volatile("bar.sync 1, 128;" ::: "memory");

            if (tid < 8) {
                asm volatile("fence.proxy.async.shared::cta;" ::: "memory");
                const unsigned int src = stg_base + (unsigned int)(q ^ 1) * 512u;
                const unsigned int pr  = (rank + (unsigned int)tid) & 7u;
                const unsigned int dst_l =
                    hb_base + (unsigned int)(q ^ 1) * 4096u + rank * 512u;
                const unsigned int mb_tgt =
                    mb_base + rank * 16u + (unsigned int)(q ^ 1) * 8u;
                unsigned int dst, rmb;
                asm("mapa.shared::cluster.u32 %0, %1, %2;"
                    : "=r"(dst) : "r"(dst_l), "r"(pr));
                asm("mapa.shared::cluster.u32 %0, %1, %2;"
                    : "=r"(rmb) : "r"(mb_tgt), "r"(pr));
                asm volatile(
                    "cp.async.bulk.shared::cluster.shared::cta.mbarrier::complete_tx::bytes "
                    "[%0], [%1], %2, [%3];"
                    :: "r"(dst), "r"(src), "r"(512u), "r"(rmb) : "memory");
            }
        }
    }

    mbar_wait(my_mb, ph0);
    asm volatile("barrier.cluster.arrive.aligned;" ::: "memory");
    asm volatile("barrier.cluster.wait.aligned;" ::: "memory");
}

extern "C" void kernel_launch(void* const* d_in, const int* in_sizes, int n_in,
                              void* d_out, int out_size) {
    const float* x  = (const float*)d_in[0];   // [64,2048,512]
    const float* Wi = (const float*)d_in[1];   // [512,512]
    const float* Ui = (const float*)d_in[2];   // [512,512]
    const float* bi = (const float*)d_in[3];   // [512]

    float* hidden = (float*)d_out;                        // [B,S,H]
    float* hlast  = hidden + (size_t)Bsz * Ssz * Hsz;     // [B,H]

    // Phase 0: fp32 -> (hi, lo) bf16 decompositions.
    conv_x<<<65536, 256>>>(x);     // 67.1M elems / 4 per thread
    conv_w<<<1024, 256>>>(Wi);

    // Phase 1: xW + b via HMMA (mma.sync bf16 x3).
    dim3 g1(8, 1024);              // N/64, M/128
    gemm_mma<<<g1, 256>>>(bi, hidden);

    // Phase 2: scan (R14 winner, unchanged).
    cudaFuncSetAttribute(rnn_scan,
                         cudaFuncAttributeMaxDynamicSharedMemorySize,
                         SMEM_TOTAL);
    rnn_scan<<<256, 256, SMEM_TOTAL>>>(Ui, hidden, hlast);
}

// round 17
// speedup vs baseline: 1.3232x; 1.3232x over previous
#include <cuda_runtime.h>
#include <cuda_bf16.h>
#include <cstdint>

#define Bsz 64
#define Ssz 2048
#define Isz 512
#define Hsz 512

// ============================================================
// Scratch: bf16 hi/lo decompositions (device globals — allowed).
// ============================================================
__device__ __nv_bfloat16 g_xhi[(size_t)Bsz * Ssz * Isz];   // 128 MB
__device__ __nv_bfloat16 g_xlo[(size_t)Bsz * Ssz * Isz];   // 128 MB
__device__ __nv_bfloat16 g_wthi[Isz * Hsz];                // W^T [n][k]
__device__ __nv_bfloat16 g_wtlo[Isz * Hsz];

// ============================================================
// conv_x: fp32 -> (hi = truncate-to-bf16, lo = exact residual rn).
// Packed ops: PRMT for hi pair, sub.rn.f32x2 for residual pair.
// ============================================================
__global__ __launch_bounds__(256) void conv_x(const float* __restrict__ x) {
    const size_t i = ((size_t)blockIdx.x * 256 + threadIdx.x) * 4;
    float4 v = *(const float4*)(x + i);
    uint32_t b[4] = {__float_as_uint(v.x), __float_as_uint(v.y),
                     __float_as_uint(v.z), __float_as_uint(v.w)};
    uint32_t hi01, hi23;
    asm("prmt.b32 %0, %1, %2, 0x7632;" : "=r"(hi01) : "r"(b[0]), "r"(b[1]));
    asm("prmt.b32 %0, %1, %2, 0x7632;" : "=r"(hi23) : "r"(b[2]), "r"(b[3]));

    uint32_t lo01, lo23;
    {
        uint32_t h0 = b[0] & 0xFFFF0000u, h1 = b[1] & 0xFFFF0000u;
        unsigned long long vp, hp, lp;
        asm("mov.b64 %0, {%1, %2};" : "=l"(vp) : "r"(b[0]), "r"(b[1]));
        asm("mov.b64 %0, {%1, %2};" : "=l"(hp) : "r"(h0), "r"(h1));
        asm("sub.rn.f32x2 %0, %1, %2;" : "=l"(lp) : "l"(vp), "l"(hp));
        uint32_t l0, l1;
        asm("mov.b64 {%0, %1}, %2;" : "=r"(l0), "=r"(l1) : "l"(lp));
        asm("cvt.rn.bf16x2.f32 %0, %1, %2;"
            : "=r"(lo01) : "f"(__uint_as_float(l1)), "f"(__uint_as_float(l0)));
    }
    {
        uint32_t h2 = b[2] & 0xFFFF0000u, h3 = b[3] & 0xFFFF0000u;
        unsigned long long vp, hp, lp;
        asm("mov.b64 %0, {%1, %2};" : "=l"(vp) : "r"(b[2]), "r"(b[3]));
        asm("mov.b64 %0, {%1, %2};" : "=l"(hp) : "r"(h2), "r"(h3));
        asm("sub.rn.f32x2 %0, %1, %2;" : "=l"(lp) : "l"(vp), "l"(hp));
        uint32_t l2, l3;
        asm("mov.b64 {%0, %1}, %2;" : "=r"(l2), "=r"(l3) : "l"(lp));
        asm("cvt.rn.bf16x2.f32 %0, %1, %2;"
            : "=r"(lo23) : "f"(__uint_as_float(l3)), "f"(__uint_as_float(l2)));
    }
    uint2 ph = make_uint2(hi01, hi23);
    uint2 pl = make_uint2(lo01, lo23);
    *(uint2*)(g_xhi + i) = ph;
    *(uint2*)(g_xlo + i) = pl;
}

__global__ __launch_bounds__(256) void conv_w(const float* __restrict__ W) {
    const int idx = blockIdx.x * 256 + threadIdx.x;   // 262144 total
    const int k = idx >> 9, n = idx & 511;
    float v = W[idx];                                  // W[k][n]
    __nv_bfloat16 h = __float2bfloat16_rn(v);
    float lo = v - __bfloat162float(h);
    __nv_bfloat16 l = __float2bfloat16_rn(lo);
    g_wthi[n * 512 + k] = h;                           // W^T [n][k]
    g_wtlo[n * 512 + k] = l;
}

// ============================================================
// Phase 1 GEMM: xW + b via mma.sync.m16n8k16, smem-staged.
// CTA 128M x 128N, 8 warps (4m x 2n), warp tile 32m x 64n.
// K chunks of 32; smem tiles AH/AL (128x32 bf16) + BH/BL
// (128n x 32k bf16), row stride 80B (conflict-free frag LDS).
// Fragment per-thread math identical to R16 (validated).
// ============================================================
#define MMA_BF16(c, a0, a1, a2, a3, b0, b1)                            \
    asm volatile(                                                      \
        "mma.sync.aligned.m16n8k16.row.col.f32.bf16.bf16.f32 "         \
        "{%0,%1,%2,%3}, {%4,%5,%6,%7}, {%8,%9}, {%0,%1,%2,%3};"        \
        : "+f"((c)[0]), "+f"((c)[1]), "+f"((c)[2]), "+f"((c)[3])       \
        : "r"(a0), "r"(a1), "r"(a2), "r"(a3), "r"(b0), "r"(b1))

#define SA_H 0
#define SA_L 10240
#define SB_H 20480
#define SB_L 30720

__global__ __launch_bounds__(256, 2) void gemm_mma2(
    const float* __restrict__ bias,
    float* __restrict__ C)          // [M,512] = xW+b
{
    __shared__ __align__(16) char sm[40960];

    const int tid  = threadIdx.x;
    const int wid  = tid >> 5;
    const int lane = tid & 31;
    const int gr   = lane >> 2;
    const int tg   = lane & 3;

    const int bm = blockIdx.y, bn = blockIdx.x;
    const int wm0 = (wid >> 1) * 32;    // local m base (0..96)
    const int wn0 = (wid & 1) * 64;     // local n base (0 or 64)

    float acc[2][8][4];
#pragma unroll
    for (int mf = 0; mf < 2; mf++)
#pragma unroll
        for (int nf = 0; nf < 8; nf++)
#pragma unroll
            for (int j = 0; j < 4; j++) acc[mf][nf][j] = 0.0f;

    for (int kc = 0; kc < 16; kc++) {
        __syncthreads();   // previous chunk's fragment reads done
        // ---- stage A tiles (hi/lo), coalesced u64 ----
#pragma unroll
        for (int i = 0; i < 4; i++) {
            const int s   = tid + i * 256;        // 0..1023
            const int row = s >> 3;
            const int col = (s & 7) * 4;
            const size_t g = (size_t)(bm * 128 + row) * 512 + kc * 32 + col;
            const int so = row * 80 + col * 2;
            *(unsigned long long*)(sm + SA_H + so) =
                *(const unsigned long long*)(g_xhi + g);
            *(unsigned long long*)(sm + SA_L + so) =
                *(const unsigned long long*)(g_xlo + g);
        }
        // ---- stage B tiles (hi/lo), coalesced uint4 ----
#pragma unroll
        for (int i = 0; i < 2; i++) {
            const int s = tid + i * 256;          // 0..511
            const int n = s >> 2;
            const int q = s & 3;                  // col = q*8 bf16 = 16B
            const size_t g = (size_t)(bn * 128 + n) * 512 + kc * 32 + q * 8;
            const int so = n * 80 + q * 16;
            *(uint4*)(sm + SB_H + so) = *(const uint4*)(g_wthi + g);
            *(uint4*)(sm + SB_L + so) = *(const uint4*)(g_wtlo + g);
        }
        __syncthreads();

#pragma unroll
        for (int ks = 0; ks < 2; ks++) {
            const int kb = (ks * 16 + tg * 2) * 2;   // k byte offset in row
            // A fragments (R16-validated mapping, now from smem)
            uint32_t ah[2][4], al[2][4];
#pragma unroll
            for (int mf = 0; mf < 2; mf++) {
                const int base = (wm0 + mf * 16 + gr) * 80 + kb;
                ah[mf][0] = *(const uint32_t*)(sm + SA_H + base);
                ah[mf][1] = *(const uint32_t*)(sm + SA_H + base + 8 * 80);
                ah[mf][2] = *(const uint32_t*)(sm + SA_H + base + 16);
                ah[mf][3] = *(const uint32_t*)(sm + SA_H + base + 8 * 80 + 16);
                al[mf][0] = *(const uint32_t*)(sm + SA_L + base);
                al[mf][1] = *(const uint32_t*)(sm + SA_L + base + 8 * 80);
                al[mf][2] = *(const uint32_t*)(sm + SA_L + base + 16);
                al[mf][3] = *(const uint32_t*)(sm + SA_L + base + 8 * 80 + 16);
            }
#pragma unroll
            for (int nf = 0; nf < 8; nf++) {
                const int bb = (wn0 + nf * 8 + gr) * 80 + kb;
                const uint32_t bh0 = *(const uint32_t*)(sm + SB_H + bb);
                const uint32_t bh1 = *(const uint32_t*)(sm + SB_H + bb + 16);
                const uint32_t bl0 = *(const uint32_t*)(sm + SB_L + bb);
                const uint32_t bl1 = *(const uint32_t*)(sm + SB_L + bb + 16);
#pragma unroll
                for (int mf = 0; mf < 2; mf++) {
                    MMA_BF16(acc[mf][nf], ah[mf][0], ah[mf][1], ah[mf][2],
                             ah[mf][3], bh0, bh1);
                    MMA_BF16(acc[mf][nf], ah[mf][0], ah[mf][1], ah[mf][2],
                             ah[mf][3], bl0, bl1);
                    MMA_BF16(acc[mf][nf], al[mf][0], al[mf][1], al[mf][2],
                             al[mf][3], bh0, bh1);
                }
            }
        }
    }

    // ---- epilogue: add bias, store fp32 ----
#pragma unroll
    for (int mf = 0; mf < 2; mf++) {
        const int row = bm * 128 + wm0 + mf * 16 + gr;
#pragma unroll
        for (int nf = 0; nf < 8; nf++) {
            const int col = bn * 128 + wn0 + nf * 8 + tg * 2;
            const float b0 = __ldg(bias + col);
            const float b1 = __ldg(bias + col + 1);
            float2 r0 = make_float2(acc[mf][nf][0] + b0, acc[mf][nf][1] + b1);
            float2 r1 = make_float2(acc[mf][nf][2] + b0, acc[mf][nf][3] + b1);
            *(float2*)(C + (size_t)row * 512 + col)       = r0;
            *(float2*)(C + (size_t)(row + 8) * 512 + col) = r1;
        }
    }
}

// ============================================================
// fast tanh + mbar_wait (unchanged)
// ============================================================
__device__ __forceinline__ float fast_tanh(float x) {
    float e;
    asm("ex2.approx.f32 %0, %1;" : "=f"(e) : "f"(x * 2.8853900817779268f));
    float r;
    asm("rcp.approx.f32 %0, %1;" : "=f"(r) : "f"(e + 1.0f));
    return fmaf(-2.0f, r, 1.0f);
}

__device__ __forceinline__ void mbar_wait(unsigned int addr, unsigned int parity) {
    unsigned int done;
    do {
        asm volatile(
            "{\n\t.reg .pred p;\n\t"
            "mbarrier.try_wait.parity.acquire.cta.shared::cta.b64 p, [%1], %2, 0x989680;\n\t"
            "selp.b32 %0, 1, 0, p;\n\t}"
            : "=r"(done) : "r"(addr), "r"(parity) : "memory");
    } while (!done);
}

// Dynamic smem layout (bytes) — scan (unchanged R14):
#define HB_OFF   0u
#define STG_OFF  8192u
#define RED_OFF  9216u
#define MB_OFF   17408u
#define USM_OFF  17536u
#define SMEM_TOTAL 83072

// ============================================================
// Phase 2: persistent cluster RNN scan — R14 winner, verbatim.
// ============================================================
__global__ void __launch_bounds__(256, 2) __cluster_dims__(8, 1, 1)
rnn_scan(const float* __restrict__ U,
         float* __restrict__ hidden,
         float* __restrict__ hlast)
{
    extern __shared__ __align__(128) char dsm[];

    const int tid  = threadIdx.x;
    unsigned int rank;
    asm("mov.u32 %0, %%cluster_ctarank;" : "=r"(rank));
    const int cid  = blockIdx.x >> 3;
    const int b0   = cid * 2;
    const int w    = tid >> 5;
    const int lane = tid & 31;
    const int gc0  = (int)rank * 64 + lane;
    const int gc1  = gc0 + 32;

    unsigned long long* Usm = (unsigned long long*)(dsm + USM_OFF);

    unsigned long long UA[32];
#pragma unroll
    for (int j = 0; j < 32; j++) {
        int k0 = w * 64 + 2 * j;
        unsigned int lo = __float_as_uint(U[(size_t)k0 * Hsz + gc0]);
        unsigned int hi = __float_as_uint(U[(size_t)(k0 + 1) * Hsz + gc0]);
        asm("mov.b64 %0, {%1, %2};" : "=l"(UA[j]) : "r"(lo), "r"(hi));
    }
    for (int j = 0; j < 32; j++) {
        int k0 = w * 64 + 2 * j;
        unsigned int lo = __float_as_uint(U[(size_t)k0 * Hsz + gc1]);
        unsigned int hi = __float_as_uint(U[(size_t)(k0 + 1) * Hsz + gc1]);
        unsigned long long u;
        asm("mov.b64 %0, {%1, %2};" : "=l"(u) : "r"(lo), "r"(hi));
        Usm[j * 256 + tid] = u;
    }

    const unsigned int hb_base =
        (unsigned int)__cvta_generic_to_shared(dsm + HB_OFF);
    const unsigned int stg_base =
        (unsigned int)__cvta_generic_to_shared(dsm + STG_OFF);
    const unsigned int mb_base =
        (unsigned int)__cvta_generic_to_shared(dsm + MB_OFF);
    float* redp = (float*)(dsm + RED_OFF);

    const unsigned int my_mb = mb_base + (unsigned int)w * 16u;

    {
        float* hz = (float*)(dsm + HB_OFF);
        for (int i = tid; i < 2048; i += 256) hz[i] = 0.0f;
    }
    if (tid == 0) {
#pragma unroll
        for (int qq = 0; qq < 8; qq++) {
#pragma unroll
            for (int b = 0; b < 2; b++)
                asm volatile("mbarrier.init.shared.b64 [%0], %1;"
                             :: "r"(mb_base + qq * 16u + b * 8u), "r"(1u)
                             : "memory");
            asm volatile("mbarrier.arrive.expect_tx.shared.b64 _, [%0], %1;"
                         :: "r"(mb_base + qq * 16u + 8u), "r"(512u) : "memory");
        }
    }
    __syncthreads();
    asm volatile("barrier.cluster.arrive.aligned;" ::: "memory");
    asm volatile("barrier.cluster.wait.aligned;" ::: "memory");

    const int ec  = tid & 63;
    const int eb  = (tid >> 6) & 1;
    const int egc = (int)rank * 64 + ec;
    const int ecomp = (ec >> 5) * 2 + eb;
    const int elane = ec & 31;
    size_t gaddr = 0;
    if (tid < 128)
        gaddr = ((size_t)(b0 + eb) * Ssz) * Hsz + egc;

    unsigned int ph0 = 0, ph1 = 0;

    for (int t = 0; t < Ssz; t++) {
        const int q = t & 1;
        const unsigned int mbq = my_mb + (unsigned int)q * 8u;

        float xw = 0.0f;
        if (tid < 128)
            xw = __ldg(hidden + gaddr);

        if (t > 0) {
            if (q == 0) { mbar_wait(mbq, ph0); ph0 ^= 1; }
            else        { mbar_wait(mbq, ph1); ph1 ^= 1; }
        }
        if (lane == 0)
            asm volatile("mbarrier.arrive.expect_tx.shared.b64 _, [%0], %1;"
                         :: "r"(mbq), "r"(512u) : "memory");

        const ulonglong2* hk =
            (const ulonglong2*)(dsm + HB_OFF + q * 4096 + w * 512);
        unsigned long long a0 = 0ull, a1 = 0ull, a2 = 0ull, a3 = 0ull;
#pragma unroll
        for (int j = 0; j < 32; j++) {
            ulonglong2 p = hk[j];
            unsigned long long ub = Usm[j * 256 + tid];
            asm("fma.rn.f32x2 %0, %1, %2, %0;" : "+l"(a0) : "l"(UA[j]), "l"(p.x));
            asm("fma.rn.f32x2 %0, %1, %2, %0;" : "+l"(a1) : "l"(UA[j]), "l"(p.y));
            asm("fma.rn.f32x2 %0, %1, %2, %0;" : "+l"(a2) : "l"(ub), "l"(p.x));
            asm("fma.rn.f32x2 %0, %1, %2, %0;" : "+l"(a3) : "l"(ub), "l"(p.y));
        }
        float s0, s1, s2, s3;
        {
            unsigned int l, h;
            asm("mov.b64 {%0, %1}, %2;" : "=r"(l), "=r"(h) : "l"(a0));
            s0 = __uint_as_float(l) + __uint_as_float(h);
            asm("mov.b64 {%0, %1}, %2;" : "=r"(l), "=r"(h) : "l"(a1));
            s1 = __uint_as_float(l) + __uint_as_float(h);
            asm("mov.b64 {%0, %1}, %2;" : "=r"(l), "=r"(h) : "l"(a2));
            s2 = __uint_as_float(l) + __uint_as_float(h);
            asm("mov.b64 {%0, %1}, %2;" : "=r"(l), "=r"(h) : "l"(a3));
            s3 = __uint_as_float(l) + __uint_as_float(h);
        }

        float* rq = redp + q * 1024;
        if (tid >= 128) {
            if (t > 0)
                asm volatile("bar.sync 3, 256;" ::: "memory");
            rq[(0 * 8 + w) * 32 + lane] = s0;
            rq[(1 * 8 + w) * 32 + lane] = s1;
            rq[(2 * 8 + w) * 32 + lane] = s2;
            rq[(3 * 8 + w) * 32 + lane] = s3;
            asm volatile("bar.arrive 2, 256;" ::: "memory");
        } else {
            rq[(0 * 8 + w) * 32 + lane] = s0;
            rq[(1 * 8 + w) * 32 + lane] = s1;
            rq[(2 * 8 + w) * 32 + lane] = s2;
            rq[(3 * 8 + w) * 32 + lane] = s3;
            asm volatile("bar.sync 2, 256;" ::: "memory");

            const float* rr = rq + ecomp * 256 + elane;
            float v = xw + (((rr[0 * 32] + rr[1 * 32]) +
                             (rr[2 * 32] + rr[3 * 32])) +
                            ((rr[4 * 32] + rr[5 * 32]) +
                             (rr[6 * 32] + rr[7 * 32])));
            v = fast_tanh(v);
            asm volatile("bar.arrive 3, 256;" ::: "memory");

            *(float*)(dsm + STG_OFF + (q ^ 1) * 512 +
                      (ec >> 1) * 16 + eb * 8 + (ec & 1) * 4) = v;

            hidden[gaddr] = v;
            if (t == Ssz - 1)
                hlast[(size_t)(b0 + eb) * Hsz + egc] = v;
            else
                gaddr += Hsz;

            asm volatile("bar.sync 1, 128;" ::: "memory");

            if (tid < 8) {
                asm volatile("fence.proxy.async.shared::cta;" ::: "memory");
                const unsigned int src = stg_base + (unsigned int)(q ^ 1) * 512u;
                const unsigned int pr  = (rank + (unsigned int)tid) & 7u;
                const unsigned int dst_l =
                    hb_base + (unsigned int)(q ^ 1) * 4096u + rank * 512u;
                const unsigned int mb_tgt =
                    mb_base + rank * 16u + (unsigned int)(q ^ 1) * 8u;
                unsigned int dst, rmb;
                asm("mapa.shared::cluster.u32 %0, %1, %2;"
                    : "=r"(dst) : "r"(dst_l), "r"(pr));
                asm("mapa.shared::cluster.u32 %0, %1, %2;"
                    : "=r"(rmb) : "r"(mb_tgt), "r"(pr));
                asm volatile(
                    "cp.async.bulk.shared::cluster.shared::cta.mbarrier::complete_tx::bytes "
                    "[%0], [%1], %2, [%3];"
                    :: "r"(dst), "r"(src), "r"(512u), "r"(rmb) : "memory");
            }
        }
    }

    mbar_wait(my_mb, ph0);
    asm volatile("barrier.cluster.arrive.aligned;" ::: "memory");
    asm volatile("barrier.cluster.wait.aligned;" ::: "memory");
}

extern "C" void kernel_launch(void* const* d_in, const int* in_sizes, int n_in,
                              void* d_out, int out_size) {
    const float* x  = (const float*)d_in[0];   // [64,2048,512]
    const float* Wi = (const float*)d_in[1];   // [512,512]
    const float* Ui = (const float*)d_in[2];   // [512,512]
    const float* bi = (const float*)d_in[3];   // [512]

    float* hidden = (float*)d_out;                        // [B,S,H]
    float* hlast  = hidden + (size_t)Bsz * Ssz * Hsz;     // [B,H]

    // Phase 0: fp32 -> (hi, lo) bf16 decompositions.
    conv_x<<<65536, 256>>>(x);
    conv_w<<<1024, 256>>>(Wi);

    // Phase 1: xW + b via HMMA, smem-staged fragments.
    dim3 g1(4, 1024);              // N/128, M/128
    gemm_mma2<<<g1, 256>>>(bi, hidden);

    // Phase 2: scan (R14 winner, unchanged).
    cudaFuncSetAttribute(rnn_scan,
                         cudaFuncAttributeMaxDynamicSharedMemorySize,
                         SMEM_TOTAL);
    rnn_scan<<<256, 256, SMEM_TOTAL>>>(Ui, hidden, hlast);
}